// round 16
// baseline (speedup 1.0000x reference)
#include <cuda_runtime.h>
#include <cuda_fp16.h>
#include <math.h>
#include <stdint.h>

#define NB 2
#define NC 128
#define HG 32
#define L 1024
#define NCOLS 2048   // NC * 16
#define KP 64        // NC/2 channel pairs

// ---- scratch (device globals; no allocation allowed) ----
__device__ uint32_t g_bdh[NB*KP*L];      // bd hi half2 [b][kp][m]
__device__ uint32_t g_bdl[NB*KP*L];      // bd lo half2
__device__ uint32_t g_fdh[NB*KP*L];      // fd hi half2
__device__ uint32_t g_fdl[NB*KP*L];      // fd lo half2
__device__ float g_ssq[NB*L];
__device__ float g_rnorm[NB*L];
__device__ float g_corr[NB*L*L];         // corr[q][p]; later reused as t2[p][q]
__device__ float g_t1[NB*L*L];           // fused scores+fuse1 output [q][p]
__device__ float g_mmk[L];
__device__ __half g_attnh[NB*L*L];       // attn [b][p][q], fp16
__device__ __half g_Wh[NB*NCOLS*L];      // W [b][n][q], fp16
__device__ float g_OP[NB*NCOLS*L];       // deconv GEMM output [b][n][p] (transposed)

// ---- helpers ----
__device__ __forceinline__ void cp_async16(uint32_t s, const void* g) {
    asm volatile("cp.async.cg.shared.global [%0], [%1], 16;" :: "r"(s), "l"(g));
}
__device__ __forceinline__ void mma_f16(float* c, const uint32_t* a, const uint32_t* b) {
    asm volatile(
        "mma.sync.aligned.m16n8k16.row.col.f32.f16.f16.f32 "
        "{%0,%1,%2,%3}, {%4,%5,%6,%7}, {%8,%9}, {%0,%1,%2,%3};"
        : "+f"(c[0]), "+f"(c[1]), "+f"(c[2]), "+f"(c[3])
        : "r"(a[0]), "r"(a[1]), "r"(a[2]), "r"(a[3]), "r"(b[0]), "r"(b[1]));
}
__device__ __forceinline__ uint32_t pack_h2(__half a, __half b) {
    return (uint32_t)__half_as_ushort(a) | ((uint32_t)__half_as_ushort(b) << 16);
}
__device__ __forceinline__ float2 h2_to_f2(uint32_t u) {
    __half2 h = *reinterpret_cast<__half2*>(&u);
    return __half22float2(h);
}

// ---- 1. downsample by 2 + fp16 hi/lo split pack (channel pairs) ----
__global__ void k_down_split(const float* __restrict__ f, const float* __restrict__ b) {
    int idx = blockIdx.x * blockDim.x + threadIdx.x;
    if (idx >= NB*KP*L) return;
    int m = idx & 1023;
    int kp = (idx >> 10) & (KP - 1);
    int bb = idx >> 16;
    int x = m & 31, y = m >> 5;
    int c0 = 2 * kp;
    size_t base0 = ((size_t)(bb * NC + c0)) * 4096 + (size_t)(2*y) * 64 + 2*x;
    size_t base1 = base0 + 4096;
    float f0 = f[base0], f1 = f[base1];
    float b0 = b[base0], b1 = b[base1];

    __half bh0 = __float2half(b0), bh1 = __float2half(b1);
    __half bl0 = __float2half(b0 - __half2float(bh0));
    __half bl1 = __float2half(b1 - __half2float(bh1));
    __half fh0 = __float2half(f0), fh1 = __float2half(f1);
    __half fl0 = __float2half(f0 - __half2float(fh0));
    __half fl1 = __float2half(f1 - __half2float(fh1));

    size_t o = (size_t)bb * KP * L + (size_t)kp * L + m;
    g_bdh[o] = pack_h2(bh0, bh1);
    g_bdl[o] = pack_h2(bl0, bl1);
    g_fdh[o] = pack_h2(fh0, fh1);
    g_fdl[o] = pack_h2(fl0, fl1);
}

// ---- 2. per-pixel sum over c of bd^2 (reconstruct from hi+lo) ----
__global__ void k_ssq() {
    int idx = blockIdx.x * blockDim.x + threadIdx.x;
    if (idx >= NB*L) return;
    int bb = idx >> 10, q = idx & 1023;
    const uint32_t* ph = g_bdh + (size_t)bb * KP * L + q;
    const uint32_t* pl = g_bdl + (size_t)bb * KP * L + q;
    float s = 0.f;
    #pragma unroll 8
    for (int kp = 0; kp < KP; kp++) {
        float2 h = h2_to_f2(ph[(size_t)kp * L]);
        float2 l = h2_to_f2(pl[(size_t)kp * L]);
        float v0 = h.x + l.x, v1 = h.y + l.y;
        s += v0 * v0 + v1 * v1;
    }
    g_ssq[idx] = s;
}

// ---- 3. patch inverse norms (3x3, zero pad) ----
__global__ void k_rnorm() {
    int idx = blockIdx.x * blockDim.x + threadIdx.x;
    if (idx >= NB*L) return;
    int bb = idx >> 10, q = idx & 1023;
    int qy = q >> 5, qx = q & 31;
    float s = 1152.0f * 0.0001f;
    for (int dy = -1; dy <= 1; dy++)
      for (int dx = -1; dx <= 1; dx++) {
        int y = qy + dy, x = qx + dx;
        if (y >= 0 && y < HG && x >= 0 && x < HG) s += g_ssq[bb*L + y*HG + x];
      }
    g_rnorm[idx] = 1.0f / sqrtf(s);
}

// =====================================================================
// GEMM1 (R14 exact, proven): fp16-split m16n8k16, 3-stage cp.async:
// corr[q,p] = sum_c bd[c,q]*fd[c,p], dropping lo·lo.
// 128x128 CTA tile, 128 threads / 4 warps (64x64 warp tile), 16 kp
// (BK=32 channels) per stage, 4 k-tiles.
// =====================================================================
#define S_LD 136                       // u32 per smem row
#define G1_TILE (16*S_LD)              // words per tile (16 kp x 128 m)
#define G1_STAGE (4*G1_TILE)           // Ahi,Alo,Bhi,Blo

__global__ void __launch_bounds__(128, 2)
mma_gemm1h(const uint32_t* __restrict__ Ah, const uint32_t* __restrict__ Al,
           const uint32_t* __restrict__ Bh, const uint32_t* __restrict__ Bl,
           float* __restrict__ Call) {
    extern __shared__ uint32_t smw[];
    const size_t bofs = (size_t)blockIdx.z * KP * L;
    float* C = Call + (size_t)blockIdx.z * (size_t)L * L;
    const int bm = blockIdx.y * 128, bn = blockIdx.x * 128;
    const int tid = threadIdx.x;
    const int warp = tid >> 5, lane = tid & 31;
    const int wm = (warp & 1) << 6, wn = (warp >> 1) << 6;
    const int r8 = lane >> 2, cc = lane & 3;

    float acc[4][8][4];
    #pragma unroll
    for (int mi = 0; mi < 4; mi++)
      #pragma unroll
      for (int ni = 0; ni < 8; ni++)
        #pragma unroll
        for (int k = 0; k < 4; k++) acc[mi][ni][k] = 0.f;

    const int lr = tid >> 3;                 // row 0..15
    const int lc = (tid & 7) * 16;           // u32 col base
    uint32_t smb = (uint32_t)__cvta_generic_to_shared(smw);

    auto load_stage = [&](int buf, int kt) {
        uint32_t sb = smb + (uint32_t)(buf * G1_STAGE) * 4u;
        size_t gro = bofs + (size_t)(kt * 16 + lr) * L;
        const uint32_t* s0 = Ah + gro + bm + lc;
        const uint32_t* s1 = Al + gro + bm + lc;
        const uint32_t* s2 = Bh + gro + bn + lc;
        const uint32_t* s3 = Bl + gro + bn + lc;
        uint32_t d = sb + (uint32_t)(lr * S_LD + lc) * 4u;
        #pragma unroll
        for (int j = 0; j < 4; j++) {
            cp_async16(d + j * 16,                      s0 + j * 4);
            cp_async16(d + j * 16 + G1_TILE * 4u,       s1 + j * 4);
            cp_async16(d + j * 16 + 2u * G1_TILE * 4u,  s2 + j * 4);
            cp_async16(d + j * 16 + 3u * G1_TILE * 4u,  s3 + j * 4);
        }
        asm volatile("cp.async.commit_group;");
    };

    load_stage(0, 0);
    load_stage(1, 1);

    const int NKT = 4;
    for (int kt = 0; kt < NKT; kt++) {
        if (kt + 2 < NKT) {
            load_stage((kt + 2) % 3, kt + 2);
            asm volatile("cp.async.wait_group 2;");
        } else if (kt == NKT - 2) {
            asm volatile("cp.async.wait_group 1;");
        } else {
            asm volatile("cp.async.wait_group 0;");
        }
        __syncthreads();

        const uint32_t* Ahi = smw + (kt % 3) * G1_STAGE;
        const uint32_t* Alo = Ahi + G1_TILE;
        const uint32_t* Bhi = Ahi + 2 * G1_TILE;
        const uint32_t* Blo = Ahi + 3 * G1_TILE;
        #pragma unroll
        for (int s = 0; s < 2; s++) {
            const int kpb = s * 8;
            uint32_t ah[4][4], al[4][4], bh[8][2], bl[8][2];
            #pragma unroll
            for (int mi = 0; mi < 4; mi++) {
                int mo = wm + mi * 16 + r8;
                const uint32_t* p0 = Ahi + (kpb + cc) * S_LD + mo;
                ah[mi][0] = p0[0];
                ah[mi][1] = p0[8];
                ah[mi][2] = p0[4 * S_LD];
                ah[mi][3] = p0[4 * S_LD + 8];
                const uint32_t* p1 = Alo + (kpb + cc) * S_LD + mo;
                al[mi][0] = p1[0];
                al[mi][1] = p1[8];
                al[mi][2] = p1[4 * S_LD];
                al[mi][3] = p1[4 * S_LD + 8];
            }
            #pragma unroll
            for (int ni = 0; ni < 8; ni++) {
                int no = wn + ni * 8 + r8;
                const uint32_t* p0 = Bhi + (kpb + cc) * S_LD + no;
                bh[ni][0] = p0[0];
                bh[ni][1] = p0[4 * S_LD];
                const uint32_t* p1 = Blo + (kpb + cc) * S_LD + no;
                bl[ni][0] = p1[0];
                bl[ni][1] = p1[4 * S_LD];
            }
            #pragma unroll
            for (int mi = 0; mi < 4; mi++)
                #pragma unroll
                for (int ni = 0; ni < 8; ni++) {
                    mma_f16(acc[mi][ni], ah[mi], bh[ni]);
                    mma_f16(acc[mi][ni], ah[mi], bl[ni]);
                    mma_f16(acc[mi][ni], al[mi], bh[ni]);
                }
        }
        __syncthreads();
    }

    #pragma unroll
    for (int mi = 0; mi < 4; mi++) {
        int r = bm + wm + mi * 16 + r8;
        #pragma unroll
        for (int ni = 0; ni < 8; ni++) {
            int col = bn + wn + ni * 8 + cc * 2;
            *(float2*)(C + (size_t)r * L + col) =
                make_float2(acc[mi][ni][0], acc[mi][ni][1]);
            *(float2*)(C + (size_t)(r + 8) * L + col) =
                make_float2(acc[mi][ni][2], acc[mi][ni][3]);
        }
    }
}

// =====================================================================
// 5+6 fused: scores (9-tap + normalize) + fuse1 (diagonal 3-tap),
// writing g_t1 directly.  Block (32,8); output tile 32(q) x 32(p).
// =====================================================================
__global__ void __launch_bounds__(256) k_scores_fuse1() {
    __shared__ float ssc[34][35];
    const int bb = blockIdx.z;
    const int p0 = blockIdx.x * 32, q0 = blockIdx.y * 32;
    const float* M = g_corr + (size_t)bb * L * L;
    const float* rn = g_rnorm + bb * L;
    float* dst = g_t1 + (size_t)bb * L * L;
    const int tid = threadIdx.y * 32 + threadIdx.x;

    for (int idx = tid; idx < 34 * 34; idx += 256) {
        int a = idx / 34, b = idx - a * 34;
        int q = q0 - 1 + a, p = p0 - 1 + b;
        float s = 0.f;
        if (q >= 0 && q < L && p >= 0 && p < L) {
            int qy = q >> 5, qx = q & 31, py = p >> 5, px = p & 31;
            #pragma unroll
            for (int dy = -1; dy <= 1; dy++) {
                int qy2 = qy + dy, py2 = py + dy;
                if (qy2 < 0 || qy2 >= HG || py2 < 0 || py2 >= HG) continue;
                #pragma unroll
                for (int dx = -1; dx <= 1; dx++) {
                    int qx2 = qx + dx, px2 = px + dx;
                    if (qx2 < 0 || qx2 >= HG || px2 < 0 || px2 >= HG) continue;
                    s += M[(size_t)(qy2 * HG + qx2) * L + (py2 * HG + px2)];
                }
            }
            s *= rn[q];
        }
        ssc[a][b] = s;
    }
    __syncthreads();

    int tx = threadIdx.x, ty = threadIdx.y;
    #pragma unroll
    for (int r = 0; r < 4; r++) {
        int a = ty + 8 * r + 1, b = tx + 1;
        float s = ssc[a][b] + ssc[a - 1][b - 1] + ssc[a + 1][b + 1];
        dst[(size_t)(q0 + ty + 8 * r) * L + p0 + tx] = s;
    }
}

// ---- 8. mask gate (batch 0 of mask) ----
__global__ void k_mm(const float* __restrict__ mask) {
    int q = blockIdx.x * blockDim.x + threadIdx.x;
    if (q >= L) return;
    int qy = q >> 5, qx = q & 31;
    float s = 0.f;
    for (int dy = -1; dy <= 1; dy++)
      for (int dx = -1; dx <= 1; dx++) {
        int y = qy + dy, x = qx + dx;
        if (y >= 0 && y < HG && x >= 0 && x < HG)
            s += mask[(size_t)(8 * y) * 256 + 8 * x];
      }
    g_mmk[q] = (s == 0.0f) ? 1.0f : 0.0f;
}

// =====================================================================
// 7a: fuse pass 2 (diagonal 3-tap in transposed flattening), writing
// t2[p][q] into g_corr (free after scores_fuse1).  Grid (32 i, 32 hf,
// NB) = 2048 blocks of (32,32).  Thread (tx,ty) computes the value at
// p = hf*32+tx, q = i*32+ty; smem transpose gives coalesced writes.
// =====================================================================
__global__ void __launch_bounds__(1024) k_fuse2t() {
    int bb = blockIdx.z, hf = blockIdx.y, i = blockIdx.x;
    int tx = threadIdx.x, ty = threadIdx.y;
    const float* T = g_t1 + (size_t)bb * L * L;
    float* dst = g_corr + (size_t)bb * L * L;
    __shared__ float red[32][33];

    float s = 0.f;
    #pragma unroll
    for (int dd = 0; dd < 3; dd++) {
        int j2 = tx * 32 + hf + dd - 1;
        int i2 = ty * 32 + i + dd - 1;
        if (j2 >= 0 && j2 < L && i2 >= 0 && i2 < L) {
            int rowi = (i2 & 31) * 32 + (i2 >> 5);
            int col  = (j2 & 31) * 32 + (j2 >> 5);
            s += T[(size_t)rowi * L + col];
        }
    }
    red[ty][tx] = s;
    __syncthreads();
    dst[(size_t)(hf * 32 + ty) * L + i * 32 + tx] = red[tx][ty];
}

// =====================================================================
// 7b: row softmax over q per (b,p): reads t2[p][q] (in g_corr),
// writes g_attnh[p][q] fp16.  Grid (L, NB), 256 threads, 4 q/thread.
// =====================================================================
__global__ void __launch_bounds__(256) k_softmax_rows() {
    int bb = blockIdx.y, p = blockIdx.x;
    const float* src = g_corr + ((size_t)bb * L + p) * L;
    __half* dst = g_attnh + ((size_t)bb * L + p) * L;
    int tid = threadIdx.x;
    __shared__ float red[8];

    float v[4], mmv[4];
    float mx = -1e30f;
    #pragma unroll
    for (int i = 0; i < 4; i++) {
        int q = tid + 256 * i;
        mmv[i] = g_mmk[q];
        v[i] = src[q] * mmv[i] * 10.0f;
        mx = fmaxf(mx, v[i]);
    }
    #pragma unroll
    for (int o = 16; o; o >>= 1) mx = fmaxf(mx, __shfl_xor_sync(0xffffffffu, mx, o));
    if ((tid & 31) == 0) red[tid >> 5] = mx;
    __syncthreads();
    float m = red[0];
    #pragma unroll
    for (int k = 1; k < 8; k++) m = fmaxf(m, red[k]);
    __syncthreads();

    float e[4];
    float sum = 0.f;
    #pragma unroll
    for (int i = 0; i < 4; i++) {
        e[i] = __expf(v[i] - m);
        sum += e[i];
    }
    #pragma unroll
    for (int o = 16; o; o >>= 1) sum += __shfl_xor_sync(0xffffffffu, sum, o);
    if ((tid & 31) == 0) red[tid >> 5] = sum;
    __syncthreads();
    float st = 0.f;
    #pragma unroll
    for (int k = 0; k < 8; k++) st += red[k];
    float inv = 1.0f / st;
    #pragma unroll
    for (int i = 0; i < 4; i++) {
        int q = tid + 256 * i;
        dst[q] = __float2half(e[i] * inv * mmv[i]);
    }
}

// ---- 10. build W fp16, N-major (2 consecutive q per thread) ----
__global__ void k_buildWh(const float* __restrict__ b_in) {
    int idx = blockIdx.x * blockDim.x + threadIdx.x;
    if (idx >= NB*NCOLS*(L/2)) return;
    int q2 = idx & 511;
    int n = (idx >> 9) & (NCOLS - 1);
    int bb = idx >> 20;
    int v = n & 3, u = (n >> 2) & 3, c = n >> 4;
    int q0 = 2 * q2;
    int qy = q0 >> 5, qx = q0 & 31;
    int by = 2 * qy + u - 1;
    int bx0 = 2 * qx + v - 1;
    float v0 = 0.f, v1 = 0.f;
    if (by >= 0 && by < 64) {
        const float* row = b_in + ((size_t)(bb * NC + c)) * 4096 + (size_t)by * 64;
        if (bx0 >= 0 && bx0 < 64)     v0 = row[bx0];
        if (bx0 + 2 >= 0 && bx0 + 2 < 64) v1 = row[bx0 + 2];
    }
    reinterpret_cast<uint32_t*>(g_Wh)[(size_t)(bb * NCOLS + n) * (L/2) + q2] =
        pack_h2(__float2half(v0), __float2half(v1));
}

// =====================================================================
// GEMM2 via fp16 m16n8k16, 3-stage cp.async pipeline, transposed out:
// OP[n,p] = sum_q W[n,q] * attn[p,q]
// A = g_Wh [2048 n][1024 q] row-major, B = g_attnh [1024 p][1024 q]
// N-major.  128x128 CTA tile, 4 warps, BK=64, 16 k-tiles.
// =====================================================================
#define H_LDW 36                       // words per smem row
#define H_STAGE_W (2*128*H_LDW)

__global__ void __launch_bounds__(128, 2)
mma_gemm2h(const __half* __restrict__ Aall, const __half* __restrict__ Ball,
           float* __restrict__ Call) {
    extern __shared__ uint32_t smw[];
    const __half* A = Aall + (size_t)blockIdx.z * (size_t)NCOLS * L;
    const __half* B = Ball + (size_t)blockIdx.z * (size_t)L * L;
    float* C = Call + (size_t)blockIdx.z * (size_t)NCOLS * L;
    const int bm = blockIdx.y * 128, bn = blockIdx.x * 128;
    const int tid = threadIdx.x;
    const int warp = tid >> 5, lane = tid & 31;
    const int wm = (warp & 1) << 6, wn = (warp >> 1) << 6;
    const int r8 = lane >> 2, cc = lane & 3;

    float acc[4][8][4];
    #pragma unroll
    for (int mi = 0; mi < 4; mi++)
      #pragma unroll
      for (int ni = 0; ni < 8; ni++)
        #pragma unroll
        for (int k = 0; k < 4; k++) acc[mi][ni][k] = 0.f;

    const __half* ag = A + (size_t)(bm + tid) * L;
    const __half* bg = B + (size_t)(bn + tid) * L;
    uint32_t smb = (uint32_t)__cvta_generic_to_shared(smw);

    auto load_stage = [&](int buf, int kt) {
        uint32_t sb = smb + (uint32_t)(buf * H_STAGE_W) * 4u;
        const __half* ag_ = ag + kt * 64;
        const __half* bg_ = bg + kt * 64;
        uint32_t as_ = sb + (uint32_t)tid * 144u;
        uint32_t bs_ = sb + 128u * 144u + (uint32_t)tid * 144u;
        #pragma unroll
        for (int i = 0; i < 8; i++) {
            cp_async16(as_ + i * 16, ag_ + i * 8);
            cp_async16(bs_ + i * 16, bg_ + i * 8);
        }
        asm volatile("cp.async.commit_group;");
    };

    load_stage(0, 0);
    load_stage(1, 1);

    const int NKT = 16;
    for (int kt = 0; kt < NKT; kt++) {
        if (kt + 2 < NKT) {
            load_stage((kt + 2) % 3, kt + 2);
            asm volatile("cp.async.wait_group 2;");
        } else if (kt == NKT - 2) {
            asm volatile("cp.async.wait_group 1;");
        } else {
            asm volatile("cp.async.wait_group 0;");
        }
        __syncthreads();

        const uint32_t* As = smw + (kt % 3) * H_STAGE_W;
        const uint32_t* Bs = As + 128 * H_LDW;
        #pragma unroll
        for (int s = 0; s < 4; s++) {
            const int kw = s * 8;
            uint32_t a[4][4], b[8][2];
            #pragma unroll
            for (int mi = 0; mi < 4; mi++) {
                const uint32_t* ap = As + (wm + mi * 16 + r8) * H_LDW + kw + cc;
                a[mi][0] = ap[0];
                a[mi][1] = ap[8 * H_LDW];
                a[mi][2] = ap[4];
                a[mi][3] = ap[8 * H_LDW + 4];
            }
            #pragma unroll
            for (int ni = 0; ni < 8; ni++) {
                const uint32_t* bp = Bs + (wn + ni * 8 + r8) * H_LDW + kw + cc;
                b[ni][0] = bp[0];
                b[ni][1] = bp[4];
            }
            #pragma unroll
            for (int mi = 0; mi < 4; mi++)
                #pragma unroll
                for (int ni = 0; ni < 8; ni++)
                    mma_f16(acc[mi][ni], a[mi], b[ni]);
        }
        __syncthreads();
    }

    #pragma unroll
    for (int mi = 0; mi < 4; mi++) {
        int row = bm + wm + mi * 16 + r8;      // n index
        #pragma unroll
        for (int ni = 0; ni < 8; ni++) {
            int col = bn + wn + ni * 8 + cc * 2;   // p index
            *(float2*)(C + (size_t)row * L + col) =
                make_float2(acc[mi][ni][0], acc[mi][ni][1]);
            *(float2*)(C + (size_t)(row + 8) * L + col) =
                make_float2(acc[mi][ni][2], acc[mi][ni][3]);
        }
    }
}

// ---- 12. overlap-add gather (deconv epilogue); OP is [b][n][p] ----
__global__ void k_gather(float* __restrict__ out) {
    int idx = blockIdx.x * blockDim.x + threadIdx.x;
    if (idx >= NB*NC*4096) return;
    int ox = idx & 63, oy = (idx >> 6) & 63, c = (idx >> 12) & 127, bb = idx >> 19;
    float s = 0.f;
    int ay = (oy + 1) & 1, ax = (ox + 1) & 1;
    const float* OPb = g_OP + (size_t)bb * NCOLS * L;
    #pragma unroll
    for (int uu = 0; uu < 2; uu++) {
        int u = ay + 2 * uu;
        int t = oy + 1 - u;
        if (t < 0) continue;
        int py = t >> 1;
        if (py >= HG) continue;
        #pragma unroll
        for (int vv = 0; vv < 2; vv++) {
            int v = ax + 2 * vv;
            int t2 = ox + 1 - v;
            if (t2 < 0) continue;
            int px = t2 >> 1;
            if (px >= HG) continue;
            s += OPb[(size_t)(c * 16 + u * 4 + v) * L + py * HG + px];
        }
    }
    out[idx] = 0.25f * s;
}

extern "C" void kernel_launch(void* const* d_in, const int* in_sizes, int n_in,
                              void* d_out, int out_size) {
    (void)in_sizes; (void)n_in; (void)out_size;
    const float* f    = (const float*)d_in[0];
    const float* b    = (const float*)d_in[1];
    const float* mask = (const float*)d_in[2];
    float* out = (float*)d_out;

    float *p_corr, *p_OP;
    uint32_t *p_bdh, *p_bdl, *p_fdh, *p_fdl;
    __half *p_attnh, *p_Wh;
    cudaGetSymbolAddress((void**)&p_corr,  g_corr);
    cudaGetSymbolAddress((void**)&p_bdh,   g_bdh);
    cudaGetSymbolAddress((void**)&p_bdl,   g_bdl);
    cudaGetSymbolAddress((void**)&p_fdh,   g_fdh);
    cudaGetSymbolAddress((void**)&p_fdl,   g_fdl);
    cudaGetSymbolAddress((void**)&p_attnh, g_attnh);
    cudaGetSymbolAddress((void**)&p_Wh,    g_Wh);
    cudaGetSymbolAddress((void**)&p_OP,    g_OP);

    const int g1_smem = 3 * G1_STAGE * 4;    // 104448 bytes
    const int g2_smem = 3 * H_STAGE_W * 4;   // 110592 bytes
    cudaFuncSetAttribute(mma_gemm1h, cudaFuncAttributeMaxDynamicSharedMemorySize, g1_smem);
    cudaFuncSetAttribute(mma_gemm2h, cudaFuncAttributeMaxDynamicSharedMemorySize, g2_smem);

    k_down_split<<<(NB*KP*L + 255) / 256, 256>>>(f, b);
    k_ssq<<<(NB*L + 255) / 256, 256>>>();
    k_rnorm<<<(NB*L + 255) / 256, 256>>>();

    // GEMM1: corr[q,p] (M=N=1024, K=128 channels) — 3x fp16-split MMA (R14 exact)
    {
        dim3 grid(L / 128, L / 128, NB);
        mma_gemm1h<<<grid, 128, g1_smem>>>(p_bdh, p_bdl, p_fdh, p_fdl, p_corr);
    }

    // fused scores + fuse1
    {
        dim3 grid(32, 32, NB);
        dim3 blk(32, 8);
        k_scores_fuse1<<<grid, blk>>>();
    }
    k_mm<<<(L + 255) / 256, 256>>>(mask);
    // fuse2 (transposed) then row softmax
    {
        dim3 grid(32, 32, NB);
        dim3 blk(32, 32);
        k_fuse2t<<<grid, blk>>>();
    }
    {
        dim3 grid(L, NB);
        k_softmax_rows<<<grid, 256>>>();
    }
    k_buildWh<<<(NB*NCOLS*(L/2) + 255) / 256, 256>>>(b);

    // GEMM2: OP[n,p] (M=2048, N=1024, K=1024) — fp16 MMA, transposed out
    {
        dim3 grid(L / 128, NCOLS / 128, NB);
        mma_gemm2h<<<grid, 128, g2_smem>>>(p_Wh, p_attnh, p_OP);
    }

    k_gather<<<(NB*NC*4096 + 255) / 256, 256>>>(out);
}